// round 8
// baseline (speedup 1.0000x reference)
#include <cuda_runtime.h>
#include <math.h>

#define T_SEQ 2048
#define D_DIM 768
#define B_BATCH 8
#define OUT_D 1536
#define SCALE 0.03608439182435161f  // 1/sqrt(768)

// Scratch: S/P matrix [B, T, T] fp32 = 134 MB.
__device__ float g_S[(size_t)B_BATCH * T_SEQ * T_SEQ];

__device__ __forceinline__ unsigned f2tf32(float f) {
    unsigned u;
    asm("cvt.rna.tf32.f32 %0, %1;" : "=r"(u) : "f"(f));
    return u;
}

__device__ __forceinline__ void mma_tf32(float c[4], unsigned a0, unsigned a1,
                                         unsigned a2, unsigned a3,
                                         unsigned b0, unsigned b1) {
    asm volatile(
        "mma.sync.aligned.m16n8k8.row.col.f32.tf32.tf32.f32 "
        "{%0,%1,%2,%3}, {%4,%5,%6,%7}, {%8,%9}, {%0,%1,%2,%3};"
        : "+f"(c[0]), "+f"(c[1]), "+f"(c[2]), "+f"(c[3])
        : "r"(a0), "r"(a1), "r"(a2), "r"(a3), "r"(b0), "r"(b1));
}

// k-major shared tiles; stride mod 32 == 8 -> fragment loads hit all 32 banks.
#define A_STRIDE 136   // 128 cols + 8 pad
#define B_STRIDE 264   // 256 cols + 8 pad

// ---------------------------------------------------------------------------
// Kernel 1: S = scale * X X^T, lower-tri 128x256 blocks. TF32 mma.
// CTA: 256 thr, 8 warps (2m x 4n), warp tile 64x64. Register-prefetch pipeline:
// next tile's LDGs are issued before the MMA phase so global latency overlaps
// compute instead of being exposed between syncs.
// ---------------------------------------------------------------------------
__global__ __launch_bounds__(256, 1) void qk_kernel(const float* __restrict__ X) {
    const int bn = blockIdx.x;   // key tile (256 wide)
    const int bi = blockIdx.y;   // query tile (128 tall)
    const int b  = blockIdx.z;
    if (2 * bn > bi) return;     // block fully above diagonal

    const float* Ag = X + ((size_t)b * T_SEQ + (size_t)bi * 128) * D_DIM;
    const float* Bg = X + ((size_t)b * T_SEQ + (size_t)bn * 256) * D_DIM;
    float* C = g_S + ((size_t)b * T_SEQ + (size_t)bi * 128) * T_SEQ + (size_t)bn * 256;

    __shared__ unsigned As[16][A_STRIDE];
    __shared__ unsigned Bs[16][B_STRIDE];

    const int tid  = threadIdx.x;
    const int lane = tid & 31;
    const int warp = tid >> 5;
    const int g    = lane >> 2;
    const int tg   = lane & 3;
    const int wm   = (warp & 1) * 64;
    const int wn   = (warp >> 1) * 64;

    const int arow = tid >> 1;        // A loader: row 0..127
    const int alh  = tid & 1;         // A loader: k half

    float c[4][8][4];
#pragma unroll
    for (int i = 0; i < 4; ++i)
#pragma unroll
        for (int j = 0; j < 8; ++j)
#pragma unroll
            for (int r = 0; r < 4; ++r) c[i][j][r] = 0.0f;

    float4 pa[2], pb[4];
    // prologue: prefetch k-tile 0
#pragma unroll
    for (int r = 0; r < 2; ++r)
        pa[r] = *reinterpret_cast<const float4*>(Ag + (size_t)arow * D_DIM + alh * 8 + r * 4);
#pragma unroll
    for (int q = 0; q < 4; ++q)
        pb[q] = *reinterpret_cast<const float4*>(Bg + (size_t)tid * D_DIM + q * 4);

    const int NK = D_DIM / 16;   // 48
    for (int kt = 0; kt < NK; ++kt) {
        // store prefetched tile: As[k][m] = Ag[m][k], Bs[k][n] = Bg[n][k]
#pragma unroll
        for (int r = 0; r < 2; ++r) {
            const int kb = alh * 8 + r * 4;
            As[kb + 0][arow] = f2tf32(pa[r].x); As[kb + 1][arow] = f2tf32(pa[r].y);
            As[kb + 2][arow] = f2tf32(pa[r].z); As[kb + 3][arow] = f2tf32(pa[r].w);
        }
#pragma unroll
        for (int q = 0; q < 4; ++q) {
            Bs[q * 4 + 0][tid] = f2tf32(pb[q].x); Bs[q * 4 + 1][tid] = f2tf32(pb[q].y);
            Bs[q * 4 + 2][tid] = f2tf32(pb[q].z); Bs[q * 4 + 3][tid] = f2tf32(pb[q].w);
        }
        __syncthreads();

        // issue next tile's LDGs (latency hidden behind MMA phase)
        if (kt + 1 < NK) {
            const int k0 = (kt + 1) * 16;
#pragma unroll
            for (int r = 0; r < 2; ++r)
                pa[r] = *reinterpret_cast<const float4*>(Ag + (size_t)arow * D_DIM + k0 + alh * 8 + r * 4);
#pragma unroll
            for (int q = 0; q < 4; ++q)
                pb[q] = *reinterpret_cast<const float4*>(Bg + (size_t)tid * D_DIM + k0 + q * 4);
        }

#pragma unroll
        for (int h = 0; h < 2; ++h) {
            const int k_ = 8 * h + tg;
            unsigned a[4][4];
#pragma unroll
            for (int mt = 0; mt < 4; ++mt) {
                const int m = wm + mt * 16 + g;
                a[mt][0] = As[k_][m];     a[mt][1] = As[k_][m + 8];
                a[mt][2] = As[k_ + 4][m]; a[mt][3] = As[k_ + 4][m + 8];
            }
#pragma unroll
            for (int nt = 0; nt < 8; ++nt) {
                const int n = wn + nt * 8 + g;
                const unsigned b0 = Bs[k_][n];
                const unsigned b1 = Bs[k_ + 4][n];
#pragma unroll
                for (int mt = 0; mt < 4; ++mt)
                    mma_tf32(c[mt][nt], a[mt][0], a[mt][1], a[mt][2], a[mt][3], b0, b1);
            }
        }
        __syncthreads();
    }

#pragma unroll
    for (int mt = 0; mt < 4; ++mt) {
#pragma unroll
        for (int nt = 0; nt < 8; ++nt) {
            const int m = wm + mt * 16 + g;
            const int n = wn + nt * 8 + 2 * tg;
            float2 v0 = make_float2(c[mt][nt][0] * SCALE, c[mt][nt][1] * SCALE);
            float2 v1 = make_float2(c[mt][nt][2] * SCALE, c[mt][nt][3] * SCALE);
            *reinterpret_cast<float2*>(&C[(size_t)m * T_SEQ + n]) = v0;
            *reinterpret_cast<float2*>(&C[(size_t)(m + 8) * T_SEQ + n]) = v1;
        }
    }
}

// ---------------------------------------------------------------------------
// Kernel 2: per-row softmax over j<=i (denominator unmasked), post-softmax
// sit_mask zeroing (no renorm). Row cached in smem. Zero-fill only to the
// 128-padded boundary PV reads. Fuses concat copy out[b,i,768:] = X[b,i,:].
// ---------------------------------------------------------------------------
__global__ __launch_bounds__(256) void softmax_concat_kernel(
    const float* __restrict__ X, const float* __restrict__ sm,
    float* __restrict__ out) {
    const int i = blockIdx.x;
    const int b = blockIdx.y;
    float* row = g_S + ((size_t)b * T_SEQ + i) * T_SEQ;
    const int len = i + 1;
    const int len_pad = ((i >> 7) + 1) << 7;
    const int tid = threadIdx.x;

    __shared__ float srow[T_SEQ];
    __shared__ float red[8];
    __shared__ float bcast;

    float v = -INFINITY;
    for (int j = tid; j < len; j += 256) {
        const float x = row[j];
        srow[j] = x;
        v = fmaxf(v, x);
    }
#pragma unroll
    for (int o = 16; o; o >>= 1) v = fmaxf(v, __shfl_xor_sync(0xffffffffu, v, o));
    if ((tid & 31) == 0) red[tid >> 5] = v;
    __syncthreads();
    if (tid == 0) {
        float t = red[0];
#pragma unroll
        for (int w = 1; w < 8; ++w) t = fmaxf(t, red[w]);
        bcast = t;
    }
    __syncthreads();
    const float m = bcast;
    __syncthreads();

    float s = 0.0f;
    for (int j = tid; j < len; j += 256) s += __expf(srow[j] - m);
#pragma unroll
    for (int o = 16; o; o >>= 1) s += __shfl_xor_sync(0xffffffffu, s, o);
    if ((tid & 31) == 0) red[tid >> 5] = s;
    __syncthreads();
    if (tid == 0) {
        float t = 0.0f;
#pragma unroll
        for (int w = 0; w < 8; ++w) t += red[w];
        bcast = t;
    }
    __syncthreads();
    const float L = bcast;

    const float mi = sm[(size_t)b * T_SEQ + i];
    const float inv = (mi != 0.0f) ? (1.0f / L) : 0.0f;

    for (int j = tid; j < len; j += 256) {
        const float mj = sm[(size_t)b * T_SEQ + j];
        row[j] = (mj != 0.0f) ? __expf(srow[j] - m) * inv : 0.0f;
    }
    for (int j = len + tid; j < len_pad; j += 256) row[j] = 0.0f;

    const float* xr = X + ((size_t)b * T_SEQ + i) * D_DIM;
    float* orow = out + ((size_t)b * T_SEQ + i) * OUT_D + D_DIM;
    for (int d = tid * 4; d < D_DIM; d += 1024)
        *reinterpret_cast<float4*>(&orow[d]) =
            *reinterpret_cast<const float4*>(&xr[d]);
}

// ---------------------------------------------------------------------------
// Kernel 3: out[:, :768] = P @ X. TF32 mma, 128x256 CTA tile, 64x64 warp tile,
// causal k-truncation, register-prefetch pipeline. Output row stride 1536.
// ---------------------------------------------------------------------------
__global__ __launch_bounds__(256, 1) void pv_kernel(const float* __restrict__ X,
                                                    float* __restrict__ out) {
    const int bn = blockIdx.x;   // d tile 0..2 (256 wide)
    const int bi = blockIdx.y;
    const int b  = blockIdx.z;

    const float* Ag = g_S + ((size_t)b * T_SEQ + (size_t)bi * 128) * T_SEQ;
    const float* Bg = X + (size_t)b * T_SEQ * D_DIM + (size_t)bn * 256;
    float* C = out + ((size_t)b * T_SEQ + (size_t)bi * 128) * OUT_D + (size_t)bn * 256;
    const int kmax = (bi + 1) * 128;

    __shared__ unsigned As[16][A_STRIDE];
    __shared__ unsigned Bs[16][B_STRIDE];

    const int tid  = threadIdx.x;
    const int lane = tid & 31;
    const int warp = tid >> 5;
    const int g    = lane >> 2;
    const int tg   = lane & 3;
    const int wm   = (warp & 1) * 64;
    const int wn   = (warp >> 1) * 64;

    const int arow = tid >> 1;
    const int alh  = tid & 1;
    const int bkr  = tid >> 4;        // B loader: k row 0..15
    const int bc   = (tid & 15) * 4;  // B loader: col base

    float c[4][8][4];
#pragma unroll
    for (int i = 0; i < 4; ++i)
#pragma unroll
        for (int j = 0; j < 8; ++j)
#pragma unroll
            for (int r = 0; r < 4; ++r) c[i][j][r] = 0.0f;

    float4 pa[2], pb[4];
    // prologue: prefetch k-tile 0
#pragma unroll
    for (int r = 0; r < 2; ++r)
        pa[r] = *reinterpret_cast<const float4*>(Ag + (size_t)arow * T_SEQ + alh * 8 + r * 4);
#pragma unroll
    for (int p = 0; p < 4; ++p)
        pb[p] = *reinterpret_cast<const float4*>(Bg + (size_t)bkr * D_DIM + bc + p * 64);

    const int NK = kmax / 16;
    for (int kt = 0; kt < NK; ++kt) {
        // store prefetched tile
#pragma unroll
        for (int r = 0; r < 2; ++r) {
            const int kb = alh * 8 + r * 4;
            As[kb + 0][arow] = f2tf32(pa[r].x); As[kb + 1][arow] = f2tf32(pa[r].y);
            As[kb + 2][arow] = f2tf32(pa[r].z); As[kb + 3][arow] = f2tf32(pa[r].w);
        }
#pragma unroll
        for (int p = 0; p < 4; ++p) {
            const int n = bc + p * 64;
            uint4 t;
            t.x = f2tf32(pb[p].x); t.y = f2tf32(pb[p].y);
            t.z = f2tf32(pb[p].z); t.w = f2tf32(pb[p].w);
            *reinterpret_cast<uint4*>(&Bs[bkr][n]) = t;
        }
        __syncthreads();

        // issue next tile's LDGs
        if (kt + 1 < NK) {
            const int k0 = (kt + 1) * 16;
#pragma unroll
            for (int r = 0; r < 2; ++r)
                pa[r] = *reinterpret_cast<const float4*>(Ag + (size_t)arow * T_SEQ + k0 + alh * 8 + r * 4);
#pragma unroll
            for (int p = 0; p < 4; ++p)
                pb[p] = *reinterpret_cast<const float4*>(Bg + (size_t)(k0 + bkr) * D_DIM + bc + p * 64);
        }

#pragma unroll
        for (int h = 0; h < 2; ++h) {
            const int k_ = 8 * h + tg;
            unsigned a[4][4];
#pragma unroll
            for (int mt = 0; mt < 4; ++mt) {
                const int m = wm + mt * 16 + g;
                a[mt][0] = As[k_][m];     a[mt][1] = As[k_][m + 8];
                a[mt][2] = As[k_ + 4][m]; a[mt][3] = As[k_ + 4][m + 8];
            }
#pragma unroll
            for (int nt = 0; nt < 8; ++nt) {
                const int n = wn + nt * 8 + g;
                const unsigned b0 = Bs[k_][n];
                const unsigned b1 = Bs[k_ + 4][n];
#pragma unroll
                for (int mt = 0; mt < 4; ++mt)
                    mma_tf32(c[mt][nt], a[mt][0], a[mt][1], a[mt][2], a[mt][3], b0, b1);
            }
        }
        __syncthreads();
    }

#pragma unroll
    for (int mt = 0; mt < 4; ++mt) {
#pragma unroll
        for (int nt = 0; nt < 8; ++nt) {
            const int m = wm + mt * 16 + g;
            const int n = wn + nt * 8 + 2 * tg;
            float2 v0 = make_float2(c[mt][nt][0], c[mt][nt][1]);
            float2 v1 = make_float2(c[mt][nt][2], c[mt][nt][3]);
            *reinterpret_cast<float2*>(&C[(size_t)m * OUT_D + n]) = v0;
            *reinterpret_cast<float2*>(&C[(size_t)(m + 8) * OUT_D + n]) = v1;
        }
    }
}

// ---------------------------------------------------------------------------
// Inputs: [0] text_inputs [8,2048,768] f32, [1] sit_mask [8,2048] f32,
// [2] proposition_matrix (unused). Output: [8,2048,1536] f32.
// ---------------------------------------------------------------------------
extern "C" void kernel_launch(void* const* d_in, const int* in_sizes, int n_in,
                              void* d_out, int out_size) {
    const float* X  = (const float*)d_in[0];
    const float* sm = (const float*)d_in[1];
    float* out = (float*)d_out;

    qk_kernel<<<dim3(8, 16, B_BATCH), 256>>>(X);
    softmax_concat_kernel<<<dim3(T_SEQ, B_BATCH), 256>>>(X, sm, out);
    pv_kernel<<<dim3(3, 16, B_BATCH), 256>>>(X, out);
}

// round 10
// speedup vs baseline: 1.1711x; 1.1711x over previous
#include <cuda_runtime.h>
#include <math.h>

#define T_SEQ 2048
#define D_DIM 768
#define B_BATCH 8
#define OUT_D 1536
#define SCALE 0.03608439182435161f  // 1/sqrt(768)

// Scratch: S/P matrix [B, T, T] fp32 = 134 MB.
__device__ float g_S[(size_t)B_BATCH * T_SEQ * T_SEQ];

__device__ __forceinline__ void mma_tf32(float c[4], unsigned a0, unsigned a1,
                                         unsigned a2, unsigned a3,
                                         unsigned b0, unsigned b1) {
    asm volatile(
        "mma.sync.aligned.m16n8k8.row.col.f32.tf32.tf32.f32 "
        "{%0,%1,%2,%3}, {%4,%5,%6,%7}, {%8,%9}, {%0,%1,%2,%3};"
        : "+f"(c[0]), "+f"(c[1]), "+f"(c[2]), "+f"(c[3])
        : "r"(a0), "r"(a1), "r"(a2), "r"(a3), "r"(b0), "r"(b1));
}

__device__ __forceinline__ void cp16(void* smem, const void* gmem) {
    unsigned s = (unsigned)__cvta_generic_to_shared(smem);
    asm volatile("cp.async.cg.shared.global [%0], [%1], 16;" :: "r"(s), "l"(gmem));
}
#define CP_COMMIT() asm volatile("cp.async.commit_group;")
#define CP_WAIT1()  asm volatile("cp.async.wait_group 1;")
#define CP_WAIT0()  asm volatile("cp.async.wait_group 0;")

// Row-major [row][k] tiles, stride 20: frag addr = 20*row + k; 20g+tg mod 32
// covers all 32 banks (20/4=5 odd) -> conflict-free. Rows 80B -> 16B aligned.
#define RK_STRIDE 20
// pv B tile [k][n] stride 136: 136tg + g mod 32 covers all banks (136%32=8).
#define BN_STRIDE 136

// ---------------------------------------------------------------------------
// Kernel 1: S = scale * X X^T, lower-tri 128x128 blocks. TF32 mma (raw fp32
// bits as tf32). 8 warps (2m x 4n), warp tile 64x32, 2 CTAs/SM.
// 2-stage cp.async double buffer: LDG latency fully hidden, no prefetch regs.
// ---------------------------------------------------------------------------
__global__ __launch_bounds__(256, 2) void qk_kernel(const float* __restrict__ X) {
    const int bj = blockIdx.x;
    const int bi = blockIdx.y;
    const int b  = blockIdx.z;
    if (bj > bi) return;

    const float* Ag = X + ((size_t)b * T_SEQ + (size_t)bi * 128) * D_DIM;
    const float* Bg = X + ((size_t)b * T_SEQ + (size_t)bj * 128) * D_DIM;
    float* C = g_S + ((size_t)b * T_SEQ + (size_t)bi * 128) * T_SEQ + (size_t)bj * 128;

    __shared__ unsigned As[2][128][RK_STRIDE];
    __shared__ unsigned Bs[2][128][RK_STRIDE];

    const int tid  = threadIdx.x;
    const int lane = tid & 31;
    const int warp = tid >> 5;
    const int g    = lane >> 2;
    const int tg   = lane & 3;
    const int wm   = (warp & 1) * 64;
    const int wn   = (warp >> 1) * 32;

    const int lrow = tid >> 1;          // loader row 0..127
    const int lch  = (tid & 1) * 8;     // loader k offset {0,8}

    float c[4][4][4];
#pragma unroll
    for (int i = 0; i < 4; ++i)
#pragma unroll
        for (int j = 0; j < 4; ++j)
#pragma unroll
            for (int r = 0; r < 4; ++r) c[i][j][r] = 0.0f;

    const int NK = D_DIM / 16;   // 48

    // prologue: tile 0 -> stage 0
    {
        const float* ga = Ag + (size_t)lrow * D_DIM + lch;
        const float* gb = Bg + (size_t)lrow * D_DIM + lch;
        cp16(&As[0][lrow][lch],     ga);
        cp16(&As[0][lrow][lch + 4], ga + 4);
        cp16(&Bs[0][lrow][lch],     gb);
        cp16(&Bs[0][lrow][lch + 4], gb + 4);
        CP_COMMIT();
    }

    for (int kt = 0; kt < NK; ++kt) {
        const int s = kt & 1;
        if (kt + 1 < NK) {
            const int k0 = (kt + 1) * 16;
            const int ns = (kt + 1) & 1;
            const float* ga = Ag + (size_t)lrow * D_DIM + k0 + lch;
            const float* gb = Bg + (size_t)lrow * D_DIM + k0 + lch;
            cp16(&As[ns][lrow][lch],     ga);
            cp16(&As[ns][lrow][lch + 4], ga + 4);
            cp16(&Bs[ns][lrow][lch],     gb);
            cp16(&Bs[ns][lrow][lch + 4], gb + 4);
            CP_COMMIT();
            CP_WAIT1();
        } else {
            CP_WAIT0();
        }
        __syncthreads();

#pragma unroll
        for (int h = 0; h < 2; ++h) {
            const int kb = 8 * h;
            unsigned a[4][4], bf[4][2];
#pragma unroll
            for (int mt = 0; mt < 4; ++mt) {
                const int m = wm + mt * 16 + g;
                a[mt][0] = As[s][m][kb + tg];
                a[mt][1] = As[s][m + 8][kb + tg];
                a[mt][2] = As[s][m][kb + tg + 4];
                a[mt][3] = As[s][m + 8][kb + tg + 4];
            }
#pragma unroll
            for (int nt = 0; nt < 4; ++nt) {
                const int n = wn + nt * 8 + g;
                bf[nt][0] = Bs[s][n][kb + tg];
                bf[nt][1] = Bs[s][n][kb + tg + 4];
            }
#pragma unroll
            for (int mt = 0; mt < 4; ++mt)
#pragma unroll
                for (int nt = 0; nt < 4; ++nt)
                    mma_tf32(c[mt][nt], a[mt][0], a[mt][1], a[mt][2], a[mt][3],
                             bf[nt][0], bf[nt][1]);
        }
        __syncthreads();
    }

#pragma unroll
    for (int mt = 0; mt < 4; ++mt) {
#pragma unroll
        for (int nt = 0; nt < 4; ++nt) {
            const int m = wm + mt * 16 + g;
            const int n = wn + nt * 8 + 2 * tg;
            float2 v0 = make_float2(c[mt][nt][0] * SCALE, c[mt][nt][1] * SCALE);
            float2 v1 = make_float2(c[mt][nt][2] * SCALE, c[mt][nt][3] * SCALE);
            *reinterpret_cast<float2*>(&C[(size_t)m * T_SEQ + n]) = v0;
            *reinterpret_cast<float2*>(&C[(size_t)(m + 8) * T_SEQ + n]) = v1;
        }
    }
}

// ---------------------------------------------------------------------------
// Kernel 2: per-row softmax over j<=i (denominator unmasked), post-softmax
// sit_mask zeroing (no renorm). Row cached in smem; exp cached between passes.
// Zero-fill only to the 128-padded boundary PV reads. Fuses concat copy.
// ---------------------------------------------------------------------------
__global__ __launch_bounds__(256) void softmax_concat_kernel(
    const float* __restrict__ X, const float* __restrict__ sm,
    float* __restrict__ out) {
    const int i = blockIdx.x;
    const int b = blockIdx.y;
    float* row = g_S + ((size_t)b * T_SEQ + i) * T_SEQ;
    const int len = i + 1;
    const int len_pad = ((i >> 7) + 1) << 7;
    const int tid = threadIdx.x;

    __shared__ float srow[T_SEQ];
    __shared__ float red[8];
    __shared__ float bcast;

    float v = -INFINITY;
    for (int j = tid; j < len; j += 256) {
        const float x = row[j];
        srow[j] = x;
        v = fmaxf(v, x);
    }
#pragma unroll
    for (int o = 16; o; o >>= 1) v = fmaxf(v, __shfl_xor_sync(0xffffffffu, v, o));
    if ((tid & 31) == 0) red[tid >> 5] = v;
    __syncthreads();
    if (tid == 0) {
        float t = red[0];
#pragma unroll
        for (int w = 1; w < 8; ++w) t = fmaxf(t, red[w]);
        bcast = t;
    }
    __syncthreads();
    const float m = bcast;
    __syncthreads();

    float s = 0.0f;
    for (int j = tid; j < len; j += 256) {
        const float e = __expf(srow[j] - m);
        srow[j] = e;            // cache exp for pass 3 (same thread, same j)
        s += e;
    }
#pragma unroll
    for (int o = 16; o; o >>= 1) s += __shfl_xor_sync(0xffffffffu, s, o);
    if ((tid & 31) == 0) red[tid >> 5] = s;
    __syncthreads();
    if (tid == 0) {
        float t = 0.0f;
#pragma unroll
        for (int w = 0; w < 8; ++w) t += red[w];
        bcast = t;
    }
    __syncthreads();
    const float L = bcast;

    const float mi = sm[(size_t)b * T_SEQ + i];
    const float inv = (mi != 0.0f) ? (1.0f / L) : 0.0f;

    for (int j = tid; j < len; j += 256) {
        const float mj = sm[(size_t)b * T_SEQ + j];
        row[j] = (mj != 0.0f) ? srow[j] * inv : 0.0f;
    }
    for (int j = len + tid; j < len_pad; j += 256) row[j] = 0.0f;

    const float* xr = X + ((size_t)b * T_SEQ + i) * D_DIM;
    float* orow = out + ((size_t)b * T_SEQ + i) * OUT_D + D_DIM;
    for (int d = tid * 4; d < D_DIM; d += 1024)
        *reinterpret_cast<float4*>(&orow[d]) =
            *reinterpret_cast<const float4*>(&xr[d]);
}

// ---------------------------------------------------------------------------
// Kernel 3: out[:, :768] = P @ X. TF32 mma, 128x128 CTA tile, 64x32 warp tile,
// causal k-truncation, 2-stage cp.async. Output row stride 1536 (concat).
// ---------------------------------------------------------------------------
__global__ __launch_bounds__(256, 2) void pv_kernel(const float* __restrict__ X,
                                                    float* __restrict__ out) {
    const int bn = blockIdx.x;   // d tile 0..5
    const int bi = blockIdx.y;
    const int b  = blockIdx.z;

    const float* Ag = g_S + ((size_t)b * T_SEQ + (size_t)bi * 128) * T_SEQ;
    const float* Bg = X + (size_t)b * T_SEQ * D_DIM + (size_t)bn * 128;
    float* C = out + ((size_t)b * T_SEQ + (size_t)bi * 128) * OUT_D + (size_t)bn * 128;

    __shared__ unsigned As[2][128][RK_STRIDE];     // P tile, row-major [m][k]
    __shared__ unsigned Bs[2][16][BN_STRIDE];      // X tile, [k][n]

    const int tid  = threadIdx.x;
    const int lane = tid & 31;
    const int warp = tid >> 5;
    const int g    = lane >> 2;
    const int tg   = lane & 3;
    const int wm   = (warp & 1) * 64;
    const int wn   = (warp >> 1) * 32;

    const int lrow = tid >> 1;          // A loader: row 0..127
    const int lch  = (tid & 1) * 8;     // A loader: k offset
    const int bkr  = tid >> 4;          // B loader: k row 0..15
    const int bnc  = (tid & 15) * 8;    // B loader: n offset (2 chunks of 4)

    float c[4][4][4];
#pragma unroll
    for (int i = 0; i < 4; ++i)
#pragma unroll
        for (int j = 0; j < 4; ++j)
#pragma unroll
            for (int r = 0; r < 4; ++r) c[i][j][r] = 0.0f;

    const int NK = (bi + 1) * 8;   // kmax/16

    {
        const float* ga = Ag + (size_t)lrow * T_SEQ + lch;
        const float* gb = Bg + (size_t)bkr * D_DIM + bnc;
        cp16(&As[0][lrow][lch],     ga);
        cp16(&As[0][lrow][lch + 4], ga + 4);
        cp16(&Bs[0][bkr][bnc],      gb);
        cp16(&Bs[0][bkr][bnc + 4],  gb + 4);
        CP_COMMIT();
    }

    for (int kt = 0; kt < NK; ++kt) {
        const int s = kt & 1;
        if (kt + 1 < NK) {
            const int k0 = (kt + 1) * 16;
            const int ns = (kt + 1) & 1;
            const float* ga = Ag + (size_t)lrow * T_SEQ + k0 + lch;
            const float* gb = Bg + (size_t)(k0 + bkr) * D_DIM + bnc;
            cp16(&As[ns][lrow][lch],     ga);
            cp16(&As[ns][lrow][lch + 4], ga + 4);
            cp16(&Bs[ns][bkr][bnc],      gb);
            cp16(&Bs[ns][bkr][bnc + 4],  gb + 4);
            CP_COMMIT();
            CP_WAIT1();
        } else {
            CP_WAIT0();
        }
        __syncthreads();

#pragma unroll
        for (int h = 0; h < 2; ++h) {
            const int kb = 8 * h;
            unsigned a[4][4], bf[4][2];
#pragma unroll
            for (int mt = 0; mt < 4; ++mt) {
                const int m = wm + mt * 16 + g;
                a[mt][0] = As[s][m][kb + tg];
                a[mt][1] = As[s][m + 8][kb + tg];
                a[mt][2] = As[s][m][kb + tg + 4];
                a[mt][3] = As[s][m + 8][kb + tg + 4];
            }
#pragma unroll
            for (int nt = 0; nt < 4; ++nt) {
                const int n = wn + nt * 8 + g;
                bf[nt][0] = Bs[s][kb + tg][n];
                bf[nt][1] = Bs[s][kb + tg + 4][n];
            }
#pragma unroll
            for (int mt = 0; mt < 4; ++mt)
#pragma unroll
                for (int nt = 0; nt < 4; ++nt)
                    mma_tf32(c[mt][nt], a[mt][0], a[mt][1], a[mt][2], a[mt][3],
                             bf[nt][0], bf[nt][1]);
        }
        __syncthreads();
    }

#pragma unroll
    for (int mt = 0; mt < 4; ++mt) {
#pragma unroll
        for (int nt = 0; nt < 4; ++nt) {
            const int m = wm + mt * 16 + g;
            const int n = wn + nt * 8 + 2 * tg;
            float2 v0 = make_float2(c[mt][nt][0], c[mt][nt][1]);
            float2 v1 = make_float2(c[mt][nt][2], c[mt][nt][3]);
            *reinterpret_cast<float2*>(&C[(size_t)m * OUT_D + n]) = v0;
            *reinterpret_cast<float2*>(&C[(size_t)(m + 8) * OUT_D + n]) = v1;
        }
    }
}

// ---------------------------------------------------------------------------
// Inputs: [0] text_inputs [8,2048,768] f32, [1] sit_mask [8,2048] f32,
// [2] proposition_matrix (unused). Output: [8,2048,1536] f32.
// ---------------------------------------------------------------------------
extern "C" void kernel_launch(void* const* d_in, const int* in_sizes, int n_in,
                              void* d_out, int out_size) {
    const float* X  = (const float*)d_in[0];
    const float* sm = (const float*)d_in[1];
    float* out = (float*)d_out;

    qk_kernel<<<dim3(16, 16, B_BATCH), 256>>>(X);
    softmax_concat_kernel<<<dim3(T_SEQ, B_BATCH), 256>>>(X, sm, out);
    pv_kernel<<<dim3(6, 16, B_BATCH), 256>>>(X, out);
}